// round 2
// baseline (speedup 1.0000x reference)
#include <cuda_runtime.h>

// PointwiseConvBlurModel: spatially-varying 17x17 blur.
// out[b,c,y,x] = sum_{kh,kw} kern[kh*17+kw, y*256+x] * img[b,c,y+kh,x+kw]
// kern = kernels[idx[0], 0]  (idx read on-device; no host sync allowed)
//
// Inputs (metadata order):
//   d_in[0] img     f32 (4,3,272,272)
//   d_in[1] kernels f32 (16,1,289,65536)
//   d_in[2] idx     i32 scalar
// Output: f32 (4,3,256,256)

#define KS      17
#define HP      256
#define WP      256
#define PIX     (HP * WP)       // 65536
#define IH      (HP + KS - 1)   // 272
#define IW      (WP + KS - 1)   // 272
#define TH      8               // output tile height
#define TW      32              // output tile width
#define SROWS   (TH + KS - 1)   // 24
#define SCOLS   (TW + KS - 1)   // 48
#define NBC     12              // B*C planes
#define THREADS 128
#define SMEM_BYTES (NBC * SROWS * SCOLS * 4)  // 55296

__global__ __launch_bounds__(THREADS)
void blur_tiled_kernel(const float* __restrict__ img,
                       const float* __restrict__ kernels,
                       const int*   __restrict__ idx,
                       float*       __restrict__ out)
{
    extern __shared__ float simg[];  // [NBC][SROWS][SCOLS]

    const int tile = blockIdx.x;
    const int x0 = (tile % (WP / TW)) * TW;
    const int y0 = (tile / (WP / TW)) * TH;
    const int tid = threadIdx.x;

    // ---- cooperative img tile load: 12 planes x 24 rows x 12 float4/row ----
    // img row start (x0 mult of 32, IW=272=4*68) is 16B-aligned.
    {
        const int row4 = SCOLS / 4;                 // 12
        const int total4 = NBC * SROWS * row4;      // 3456
        #pragma unroll 4
        for (int i = tid; i < total4; i += THREADS) {
            const int c4 = i % row4;
            const int r  = (i / row4) % SROWS;
            const int bc = i / (row4 * SROWS);
            const float4 v = *(const float4*)(img + ((size_t)bc * IH + (y0 + r)) * IW + x0 + c4 * 4);
            *(float4*)(simg + (bc * SROWS + r) * SCOLS + c4 * 4) = v;
        }
    }
    __syncthreads();

    // ---- each thread: 2 adjacent output pixels, all 12 (b,c) planes ----
    const int tx = tid & 15;        // 0..15  -> x pair
    const int ty = tid >> 4;        // 0..7   -> row within tile
    const int lx = tx * 2;
    const int p  = (y0 + ty) * WP + x0 + lx;   // global pixel index (even)

    const float* kp = kernels + (size_t)idx[0] * (KS * KS) * (size_t)PIX + p;

    float2 acc[NBC];
    #pragma unroll
    for (int bc = 0; bc < NBC; bc++) acc[bc] = make_float2(0.f, 0.f);

    for (int kh = 0; kh < KS; kh++) {
        // Stream the 17 per-pixel weights for this tap row (float2 = both pixels).
        // 17 independent LDG.64 -> deep MLP against DRAM.
        float2 w[KS];
        #pragma unroll
        for (int kw = 0; kw < KS; kw++)
            w[kw] = *(const float2*)(kp + (size_t)(kh * KS + kw) * PIX);

        #pragma unroll
        for (int bc = 0; bc < NBC; bc++) {
            // Register-cache the 18-wide img span for this (bc, kh) row:
            // reused by all 17 taps (3.4x LDS reduction vs per-tap loads).
            const float* row = simg + (bc * SROWS + (ty + kh)) * SCOLS + lx;
            float iv[KS + 1];
            #pragma unroll
            for (int j = 0; j < KS + 1; j += 2) {
                const float2 t = *(const float2*)(row + j);  // lx even -> aligned
                iv[j] = t.x; iv[j + 1] = t.y;
            }
            #pragma unroll
            for (int kw = 0; kw < KS; kw++) {
                acc[bc].x = fmaf(w[kw].x, iv[kw],     acc[bc].x);
                acc[bc].y = fmaf(w[kw].y, iv[kw + 1], acc[bc].y);
            }
        }
    }

    #pragma unroll
    for (int bc = 0; bc < NBC; bc++)
        *(float2*)(out + (size_t)bc * PIX + p) = acc[bc];
}

extern "C" void kernel_launch(void* const* d_in, const int* in_sizes, int n_in,
                              void* d_out, int out_size)
{
    const float* img     = (const float*)d_in[0];
    const float* kernels = (const float*)d_in[1];
    const int*   idx     = (const int*)d_in[2];
    float*       out     = (float*)d_out;

    // 55.3 KB dynamic smem > 48 KB default: opt in (idempotent, host-side,
    // not a stream op -> graph-capture safe).
    static bool attr_set = false;
    if (!attr_set) {
        cudaFuncSetAttribute(blur_tiled_kernel,
                             cudaFuncAttributeMaxDynamicSharedMemorySize,
                             SMEM_BYTES);
        attr_set = true;
    }

    const int grid = (WP / TW) * (HP / TH);  // 8 * 32 = 256 tiles
    blur_tiled_kernel<<<grid, THREADS, SMEM_BYTES>>>(img, kernels, idx, out);
}

// round 7
// speedup vs baseline: 1.5908x; 1.5908x over previous
#include <cuda_runtime.h>

// PointwiseConvBlurModel: spatially-varying 17x17 blur.
// out[b,c,y,x] = sum_{kh,kw} kern[kh*17+kw, y*256+x] * img[b,c,y+kh,x+kw]
// kern = kernels[idx[0], 0]
//
// R3: plane-split-in-CTA. 3 groups x 128 px-threads = 384 thr/CTA, each thread
// 2 px x 4 planes. Weight loads are triplicated in issue but identical in
// address -> L1 hits; DRAM traffic unchanged (~76MB weights). 2 CTAs/SM via
// __launch_bounds__(384,2): 24 warps/SM vs 7 before.

#define KS      17
#define HP      256
#define WP      256
#define PIX     (HP * WP)       // 65536
#define IH      (HP + KS - 1)   // 272
#define IW      (WP + KS - 1)   // 272
#define TH      8               // output tile height
#define TW      32              // output tile width
#define SROWS   (TH + KS - 1)   // 24
#define SCOLS   (TW + KS - 1)   // 48
#define NBC     12              // B*C planes
#define GROUPS  3
#define PL      (NBC / GROUPS)  // 4 planes per thread
#define THREADS (128 * GROUPS)  // 384
#define SMEM_BYTES (NBC * SROWS * SCOLS * 4)  // 55296

__global__ __launch_bounds__(THREADS, 2)
void blur_tiled_kernel(const float* __restrict__ img,
                       const float* __restrict__ kernels,
                       const int*   __restrict__ idx,
                       float*       __restrict__ out)
{
    extern __shared__ float simg[];  // [NBC][SROWS][SCOLS]

    const int tile = blockIdx.x;
    const int x0 = (tile % (WP / TW)) * TW;
    const int y0 = (tile / (WP / TW)) * TH;
    const int tid = threadIdx.x;

    // ---- cooperative img tile load: 12 planes x 24 rows x 12 float4/row ----
    {
        const int row4 = SCOLS / 4;                 // 12
        const int total4 = NBC * SROWS * row4;      // 3456
        #pragma unroll 3
        for (int i = tid; i < total4; i += THREADS) {
            const int c4 = i % row4;
            const int r  = (i / row4) % SROWS;
            const int bc = i / (row4 * SROWS);
            const float4 v = *(const float4*)(img + ((size_t)bc * IH + (y0 + r)) * IW + x0 + c4 * 4);
            *(float4*)(simg + (bc * SROWS + r) * SCOLS + c4 * 4) = v;
        }
    }
    __syncthreads();

    // ---- group g handles planes [4g, 4g+4); 128 px-threads per group ----
    const int grp    = tid >> 7;          // 0..2
    const int wg_tid = tid & 127;
    const int tx = wg_tid & 15;           // x pair 0..15
    const int ty = wg_tid >> 4;           // row 0..7
    const int lx = tx * 2;
    const int p  = (y0 + ty) * WP + x0 + lx;
    const int bc0 = grp * PL;

    const float* kp = kernels + (size_t)idx[0] * (KS * KS) * (size_t)PIX + p;

    float2 acc[PL];
    #pragma unroll
    for (int q = 0; q < PL; q++) acc[q] = make_float2(0.f, 0.f);

    for (int kh = 0; kh < KS; kh++) {
        // 17 per-pixel weight pairs for this tap row. Same addresses in all
        // 3 groups -> 1 DRAM fetch + L1 hits. 17-deep MLP.
        float2 w[KS];
        #pragma unroll
        for (int kw = 0; kw < KS; kw++)
            w[kw] = *(const float2*)(kp + (size_t)(kh * KS + kw) * PIX);

        #pragma unroll
        for (int q = 0; q < PL; q++) {
            const float* row = simg + ((bc0 + q) * SROWS + (ty + kh)) * SCOLS + lx;
            float iv[KS + 1];
            #pragma unroll
            for (int j = 0; j < KS + 1; j += 2) {
                const float2 t = *(const float2*)(row + j);  // lx even -> 8B aligned
                iv[j] = t.x; iv[j + 1] = t.y;
            }
            #pragma unroll
            for (int kw = 0; kw < KS; kw++) {
                acc[q].x = fmaf(w[kw].x, iv[kw],     acc[q].x);
                acc[q].y = fmaf(w[kw].y, iv[kw + 1], acc[q].y);
            }
        }
    }

    #pragma unroll
    for (int q = 0; q < PL; q++)
        *(float2*)(out + (size_t)(bc0 + q) * PIX + p) = acc[q];
}

extern "C" void kernel_launch(void* const* d_in, const int* in_sizes, int n_in,
                              void* d_out, int out_size)
{
    const float* img     = (const float*)d_in[0];
    const float* kernels = (const float*)d_in[1];
    const int*   idx     = (const int*)d_in[2];
    float*       out     = (float*)d_out;

    static bool attr_set = false;
    if (!attr_set) {
        cudaFuncSetAttribute(blur_tiled_kernel,
                             cudaFuncAttributeMaxDynamicSharedMemorySize,
                             SMEM_BYTES);
        attr_set = true;
    }

    const int grid = (WP / TW) * (HP / TH);  // 256 tiles -> single wave at 2 CTA/SM
    blur_tiled_kernel<<<grid, THREADS, SMEM_BYTES>>>(img, kernels, idx, out);
}

// round 9
// speedup vs baseline: 1.8119x; 1.1390x over previous
#include <cuda_runtime.h>

// PointwiseConvBlurModel: spatially-varying 17x17 blur.
// out[b,c,y,x] = sum_{kh,kw} kern[kh*17+kw, y*256+x] * img[b,c,y+kh,x+kw]
// kern = kernels[idx[0], 0]
//
// R7: 4 px/thread (float4 everywhere). 3 groups x 64 px-threads = 192 thr/CTA,
// each thread 4 px x 4 planes. LDS traffic/elem 612->340 B, LDS instrs -2.8x,
// LDG instrs -2x (bytes unchanged). Grid 256 CTAs limits residency to <=2/SM,
// so register budget is generous (no launch_bounds reg squeeze).

#define KS      17
#define HP      256
#define WP      256
#define PIX     (HP * WP)       // 65536
#define IH      (HP + KS - 1)   // 272
#define IW      (WP + KS - 1)   // 272
#define TH      8               // output tile height
#define TW      32              // output tile width
#define SROWS   (TH + KS - 1)   // 24
#define SCOLS   (TW + KS - 1)   // 48
#define NBC     12              // B*C planes
#define GROUPS  3
#define PL      (NBC / GROUPS)  // 4 planes per thread
#define PXT     64              // px-threads per group (TH * TW / 4)
#define THREADS (PXT * GROUPS)  // 192
#define SMEM_BYTES (NBC * SROWS * SCOLS * 4)  // 55296

__global__ __launch_bounds__(THREADS, 2)
void blur_tiled_kernel(const float* __restrict__ img,
                       const float* __restrict__ kernels,
                       const int*   __restrict__ idx,
                       float*       __restrict__ out)
{
    extern __shared__ float simg[];  // [NBC][SROWS][SCOLS]

    const int tile = blockIdx.x;
    const int x0 = (tile % (WP / TW)) * TW;
    const int y0 = (tile / (WP / TW)) * TH;
    const int tid = threadIdx.x;

    // ---- cooperative img tile load: 12 planes x 24 rows x 12 float4/row ----
    {
        const int row4 = SCOLS / 4;                 // 12
        const int total4 = NBC * SROWS * row4;      // 3456
        #pragma unroll 6
        for (int i = tid; i < total4; i += THREADS) {
            const int c4 = i % row4;
            const int r  = (i / row4) % SROWS;
            const int bc = i / (row4 * SROWS);
            const float4 v = *(const float4*)(img + ((size_t)bc * IH + (y0 + r)) * IW + x0 + c4 * 4);
            *(float4*)(simg + (bc * SROWS + r) * SCOLS + c4 * 4) = v;
        }
    }
    __syncthreads();

    // ---- group g handles planes [4g, 4g+4); 64 px-threads per group,
    //      each owning a 4-px x-quad ----
    const int grp    = tid / PXT;         // 0..2
    const int wg_tid = tid % PXT;         // 0..63
    const int qx = wg_tid & 7;            // x quad 0..7
    const int ty = wg_tid >> 3;           // row 0..7
    const int lx = qx * 4;                // 16B-aligned x offset
    const int p  = (y0 + ty) * WP + x0 + lx;
    const int bc0 = grp * PL;

    const float* kp = kernels + (size_t)idx[0] * (KS * KS) * (size_t)PIX + p;

    float4 acc[PL];
    #pragma unroll
    for (int q = 0; q < PL; q++) acc[q] = make_float4(0.f, 0.f, 0.f, 0.f);

    for (int kh = 0; kh < KS; kh++) {
        // 17 per-pixel weight quads for this tap row (LDG.128, 17-deep MLP).
        // Identical addresses across the 3 groups -> L1 hits.
        float4 w[KS];
        #pragma unroll
        for (int kw = 0; kw < KS; kw++)
            w[kw] = *(const float4*)(kp + (size_t)(kh * KS + kw) * PIX);

        #pragma unroll
        for (int q = 0; q < PL; q++) {
            // 20-wide img span for this (plane, kh) row: 5 aligned LDS.128,
            // reused by all 17 taps.
            const float* row = simg + ((bc0 + q) * SROWS + (ty + kh)) * SCOLS + lx;
            float iv[KS + 3];
            #pragma unroll
            for (int j = 0; j < KS + 3; j += 4) {
                const float4 t = *(const float4*)(row + j);
                iv[j] = t.x; iv[j + 1] = t.y; iv[j + 2] = t.z; iv[j + 3] = t.w;
            }
            #pragma unroll
            for (int kw = 0; kw < KS; kw++) {
                acc[q].x = fmaf(w[kw].x, iv[kw],     acc[q].x);
                acc[q].y = fmaf(w[kw].y, iv[kw + 1], acc[q].y);
                acc[q].z = fmaf(w[kw].z, iv[kw + 2], acc[q].z);
                acc[q].w = fmaf(w[kw].w, iv[kw + 3], acc[q].w);
            }
        }
    }

    #pragma unroll
    for (int q = 0; q < PL; q++)
        *(float4*)(out + (size_t)(bc0 + q) * PIX + p) = acc[q];
}

extern "C" void kernel_launch(void* const* d_in, const int* in_sizes, int n_in,
                              void* d_out, int out_size)
{
    const float* img     = (const float*)d_in[0];
    const float* kernels = (const float*)d_in[1];
    const int*   idx     = (const int*)d_in[2];
    float*       out     = (float*)d_out;

    static bool attr_set = false;
    if (!attr_set) {
        cudaFuncSetAttribute(blur_tiled_kernel,
                             cudaFuncAttributeMaxDynamicSharedMemorySize,
                             SMEM_BYTES);
        attr_set = true;
    }

    const int grid = (WP / TW) * (HP / TH);  // 256 tiles
    blur_tiled_kernel<<<grid, THREADS, SMEM_BYTES>>>(img, kernels, idx, out);
}

// round 12
// speedup vs baseline: 1.8312x; 1.0106x over previous
#include <cuda_runtime.h>

// PointwiseConvBlurModel: spatially-varying 17x17 blur.
// out[b,c,y,x] = sum_{kh,kw} kern[kh*17+kw, y*256+x] * img[b,c,y+kh,x+kw]
// kern = kernels[idx[0], 0]
//
// R9: TH 8->4. grid 512 CTAs (load balance 3.46/SM vs 1.73), smem 45KB ->
// 4 CTAs/SM resident = 4 independent weight streams per SM hiding DRAM
// latency. Each group is exactly one warp (qx 0..7 x ty 0..3), LDS.128
// conflict-free (row stride 48 floats = bank shift 16/ty).

#define KS      17
#define HP      256
#define WP      256
#define PIX     (HP * WP)       // 65536
#define IH      (HP + KS - 1)   // 272
#define IW      (WP + KS - 1)   // 272
#define TH      4               // output tile height
#define TW      32              // output tile width
#define SROWS   (TH + KS - 1)   // 20
#define SCOLS   (TW + KS - 1)   // 48
#define NBC     12              // B*C planes
#define GROUPS  3
#define PL      (NBC / GROUPS)  // 4 planes per thread
#define PXT     (TH * TW / 4)   // 32 px-threads per group (1 warp)
#define THREADS (PXT * GROUPS)  // 96
#define SMEM_BYTES (NBC * SROWS * SCOLS * 4)  // 46080

__global__ __launch_bounds__(THREADS, 4)
void blur_tiled_kernel(const float* __restrict__ img,
                       const float* __restrict__ kernels,
                       const int*   __restrict__ idx,
                       float*       __restrict__ out)
{
    extern __shared__ float simg[];  // [NBC][SROWS][SCOLS]

    const int tile = blockIdx.x;
    const int x0 = (tile % (WP / TW)) * TW;
    const int y0 = (tile / (WP / TW)) * TH;
    const int tid = threadIdx.x;

    // ---- cooperative img tile load: 12 planes x 20 rows x 12 float4/row ----
    {
        const int row4 = SCOLS / 4;                 // 12
        const int total4 = NBC * SROWS * row4;      // 2880
        #pragma unroll 6
        for (int i = tid; i < total4; i += THREADS) {
            const int c4 = i % row4;
            const int r  = (i / row4) % SROWS;
            const int bc = i / (row4 * SROWS);
            const float4 v = *(const float4*)(img + ((size_t)bc * IH + (y0 + r)) * IW + x0 + c4 * 4);
            *(float4*)(simg + (bc * SROWS + r) * SCOLS + c4 * 4) = v;
        }
    }
    __syncthreads();

    // ---- group g = warp g handles planes [4g, 4g+4); each thread a 4-px quad ----
    const int grp    = tid / PXT;         // 0..2
    const int wg_tid = tid % PXT;         // 0..31
    const int qx = wg_tid & 7;            // x quad 0..7
    const int ty = wg_tid >> 3;           // row 0..3
    const int lx = qx * 4;                // 16B-aligned x offset
    const int p  = (y0 + ty) * WP + x0 + lx;
    const int bc0 = grp * PL;

    const float* kp = kernels + (size_t)idx[0] * (KS * KS) * (size_t)PIX + p;

    float4 acc[PL];
    #pragma unroll
    for (int q = 0; q < PL; q++) acc[q] = make_float4(0.f, 0.f, 0.f, 0.f);

    for (int kh = 0; kh < KS; kh++) {
        // 17 per-pixel weight quads for this tap row (LDG.128, 17-deep MLP).
        // Identical addresses across the 3 groups -> L1 merge/hit.
        float4 w[KS];
        #pragma unroll
        for (int kw = 0; kw < KS; kw++)
            w[kw] = *(const float4*)(kp + (size_t)(kh * KS + kw) * PIX);

        #pragma unroll
        for (int q = 0; q < PL; q++) {
            // 20-wide img span for this (plane, kh) row: 5 aligned LDS.128,
            // reused by all 17 taps.
            const float* row = simg + ((bc0 + q) * SROWS + (ty + kh)) * SCOLS + lx;
            float iv[KS + 3];
            #pragma unroll
            for (int j = 0; j < KS + 3; j += 4) {
                const float4 t = *(const float4*)(row + j);
                iv[j] = t.x; iv[j + 1] = t.y; iv[j + 2] = t.z; iv[j + 3] = t.w;
            }
            #pragma unroll
            for (int kw = 0; kw < KS; kw++) {
                acc[q].x = fmaf(w[kw].x, iv[kw],     acc[q].x);
                acc[q].y = fmaf(w[kw].y, iv[kw + 1], acc[q].y);
                acc[q].z = fmaf(w[kw].z, iv[kw + 2], acc[q].z);
                acc[q].w = fmaf(w[kw].w, iv[kw + 3], acc[q].w);
            }
        }
    }

    #pragma unroll
    for (int q = 0; q < PL; q++)
        *(float4*)(out + (size_t)(bc0 + q) * PIX + p) = acc[q];
}

extern "C" void kernel_launch(void* const* d_in, const int* in_sizes, int n_in,
                              void* d_out, int out_size)
{
    const float* img     = (const float*)d_in[0];
    const float* kernels = (const float*)d_in[1];
    const int*   idx     = (const int*)d_in[2];
    float*       out     = (float*)d_out;

    static bool attr_set = false;
    if (!attr_set) {
        cudaFuncSetAttribute(blur_tiled_kernel,
                             cudaFuncAttributeMaxDynamicSharedMemorySize,
                             SMEM_BYTES);
        attr_set = true;
    }

    const int grid = (WP / TW) * (HP / TH);  // 8 * 64 = 512 tiles
    blur_tiled_kernel<<<grid, THREADS, SMEM_BYTES>>>(img, kernels, idx, out);
}